// round 8
// baseline (speedup 1.0000x reference)
#include <cuda_runtime.h>
#include <cuda_fp16.h>
#include <cstdint>

// ============================================================================
// HiPPO-LegT scan via chunked GEMM on mma.sync (HMMA fp16, base sm_103).
//   c_t = A c_{t-1} + f_t B ;  out (512, 2048, 64)
// Chunk T=16:  OUT[c][(j,n)] = sum_k X[c][k] * G[(j,n)][k],  K = 80.
// fp16 2-pass: X = Xhi + Xlo (near-exact split), G fp16 -> rel_err ~2e-4.
// R8: ONE prep kernel (per-CTA binary powering), GEMM with A-frags reloaded
// from resident X smem (better occupancy) and jt split over grid.y.
// ============================================================================

static constexpr int TCH    = 16;
static constexpr int NCHUNK = 32;
static constexpr int NSEQ   = 2048;
static constexpr int NCOLS  = NSEQ * NCHUNK;   // 65536
static constexpr int KREAL  = 80;
static constexpr int SEQLEN = 512;
static constexpr int KPADB  = 176;             // smem row pitch bytes (88 halves)

// ---- device scratch (static; no cudaMalloc) ----
__device__ __align__(16) float   g_Apow16[4096];
__device__ __align__(16) float   g_Kvec[16 * 64];
__device__ __align__(16) __half  g_Gh [1024 * KREAL];
__device__ __align__(16) __half  g_Xhi[(size_t)NCOLS * KREAL];
__device__ __align__(16) __half  g_Xlo[(size_t)NCOLS * KREAL];

// ---- packed f32x2 helpers ----
__device__ __forceinline__ double fma2(double a, double b, double c) {
    double d; asm("fma.rn.f32x2 %0, %1, %2, %3;" : "=d"(d) : "d"(a), "d"(b), "d"(c)); return d;
}
__device__ __forceinline__ double add2(double a, double b) {
    double d; asm("add.rn.f32x2 %0, %1, %2;" : "=d"(d) : "d"(a), "d"(b)); return d;
}
__device__ __forceinline__ double pack2(float lo, float hi) {
    double d; asm("mov.b64 %0, {%1, %2};" : "=d"(d) : "f"(lo), "f"(hi)); return d;
}
__device__ __forceinline__ void unpack2(double d, float& lo, float& hi) {
    asm("mov.b64 {%0, %1}, %2;" : "=f"(lo), "=f"(hi) : "d"(d));
}

// ---- mma / ldmatrix / cp.async ----
__device__ __forceinline__ uint32_t smem_u32(const void* p) {
    uint32_t a;
    asm("{ .reg .u64 t; cvta.to.shared.u64 t, %1; cvt.u32.u64 %0, t; }" : "=r"(a) : "l"(p));
    return a;
}
__device__ __forceinline__ void mma16816(float* d, const uint32_t* a, uint32_t b0, uint32_t b1) {
    asm volatile(
        "mma.sync.aligned.m16n8k16.row.col.f32.f16.f16.f32 "
        "{%0,%1,%2,%3}, {%4,%5,%6,%7}, {%8,%9}, {%0,%1,%2,%3};\n"
        : "+f"(d[0]), "+f"(d[1]), "+f"(d[2]), "+f"(d[3])
        : "r"(a[0]), "r"(a[1]), "r"(a[2]), "r"(a[3]), "r"(b0), "r"(b1));
}
__device__ __forceinline__ void ldsm_x4(uint32_t* r, uint32_t addr) {
    asm volatile("ldmatrix.sync.aligned.m8n8.x4.shared.b16 {%0,%1,%2,%3}, [%4];"
                 : "=r"(r[0]), "=r"(r[1]), "=r"(r[2]), "=r"(r[3]) : "r"(addr));
}
__device__ __forceinline__ void cp_async16(uint32_t smem, const void* g) {
    asm volatile("cp.async.cg.shared.global [%0], [%1], 16;" :: "r"(smem), "l"(g));
}
__device__ __forceinline__ void cp_commit() { asm volatile("cp.async.commit_group;" ::: "memory"); }
__device__ __forceinline__ void cp_wait0()  { asm volatile("cp.async.wait_group 0;"  ::: "memory"); }

// ============================================================================
// Prep: ONE launch, 16 CTAs x 1024 threads.
// CTA j: A^(j+1) via binary square-and-multiply (in-place smem matmuls),
// K_d = A^d B chain (d<=j), writes G rows [j*64, j*64+64).
// CTA 15 additionally writes g_Apow16 (=A^16) and g_Kvec (full chain).
// ============================================================================
__global__ __launch_bounds__(1024) void prep_kernel(const float* __restrict__ A,
                                                    const float* __restrict__ Bvec) {
    __shared__ __align__(16) float sA[4096];
    __shared__ __align__(16) float sR[4096];
    __shared__ __align__(16) float sK[16 * 64];
    const int t = threadIdx.x;
    const int j = blockIdx.x;        // 0..15, p = j+1
    const int p = j + 1;

    for (int i = t; i < 4096; i += 1024) {
        const float v = A[i];
        sA[i] = v; sR[i] = v;
    }
    if (t < 64) sK[t] = Bvec[t];
    __syncthreads();

    // ---- K chain: K_d = A @ K_{d-1}, d = 1..j ----
    for (int d = 1; d <= j; d++) {
        float acc = 0.0f;
        if (t < 64) {
            const float4* ar = reinterpret_cast<const float4*>(&sA[t * 64]);
            const float4* kr = reinterpret_cast<const float4*>(&sK[(d - 1) * 64]);
            float s0 = 0.f, s1 = 0.f, s2 = 0.f, s3 = 0.f;
            #pragma unroll
            for (int v = 0; v < 16; v++) {
                const float4 a = ar[v], b = kr[v];
                s0 = fmaf(a.x, b.x, s0); s1 = fmaf(a.y, b.y, s1);
                s2 = fmaf(a.z, b.z, s2); s3 = fmaf(a.w, b.w, s3);
            }
            acc = (s0 + s1) + (s2 + s3);
        }
        __syncthreads();
        if (t < 64) sK[d * 64 + t] = acc;
        __syncthreads();
    }

    // ---- binary powering: sR := A^p ----
    const int row  = t >> 4;
    const int col4 = (t & 15) * 4;
    const int msb  = 31 - __clz(p);

    auto matmul_into_R = [&](const float* L, const float* R) {
        // out[row][col4..col4+3] = sum_m L[row][m] * R[m][col4..]
        float4 acc0 = make_float4(0.f, 0.f, 0.f, 0.f);
        float4 acc1 = make_float4(0.f, 0.f, 0.f, 0.f);
        #pragma unroll 8
        for (int m = 0; m < 64; m += 2) {
            const float a0 = L[row * 64 + m];
            const float a1 = L[row * 64 + m + 1];
            const float4 b0 = *reinterpret_cast<const float4*>(&R[m * 64 + col4]);
            const float4 b1 = *reinterpret_cast<const float4*>(&R[(m + 1) * 64 + col4]);
            acc0.x = fmaf(a0, b0.x, acc0.x); acc0.y = fmaf(a0, b0.y, acc0.y);
            acc0.z = fmaf(a0, b0.z, acc0.z); acc0.w = fmaf(a0, b0.w, acc0.w);
            acc1.x = fmaf(a1, b1.x, acc1.x); acc1.y = fmaf(a1, b1.y, acc1.y);
            acc1.z = fmaf(a1, b1.z, acc1.z); acc1.w = fmaf(a1, b1.w, acc1.w);
        }
        acc0.x += acc1.x; acc0.y += acc1.y; acc0.z += acc1.z; acc0.w += acc1.w;
        __syncthreads();
        *reinterpret_cast<float4*>(&sR[row * 64 + col4]) = acc0;
        __syncthreads();
    };

    for (int b = msb - 1; b >= 0; b--) {
        matmul_into_R(sR, sR);                   // square
        if (p & (1 << b)) matmul_into_R(sR, sA); // multiply
    }

    // ---- outputs ----
    if (j == 15) {
        for (int i = t; i < 4096; i += 1024) g_Apow16[i] = sR[i];
        g_Kvec[t & 1023] = sK[t & 1023];         // t covers 0..1023
    }
    for (int idx = t; idx < 64 * KREAL; idx += 1024) {
        const int n = idx / KREAL, k = idx % KREAL;
        float v;
        if (k < 64) v = sR[n * 64 + k];
        else {
            const int d = j - (k - 64);
            v = (d < 0) ? 0.0f : sK[d * 64 + n];
        }
        g_Gh[(size_t)(j * 64 + n) * KREAL + k] = __float2half(v);
    }
}

// ============================================================================
// Phase 1: boundary scan (fp32, f32x2) + X build (fp16 hi/lo). 2048 x 64.
// ============================================================================
__global__ __launch_bounds__(64) void phase1_kernel(const float* __restrict__ xin) {
    const int seq = blockIdx.x, n = threadIdx.x;
    __shared__ __align__(16) float c_sm[2][64];
    __shared__ __align__(16) float f_sm[2][16];

    double a16[32];
    {
        const double* r = reinterpret_cast<const double*>(&g_Apow16[n * 64]);
        #pragma unroll
        for (int i = 0; i < 32; i++) a16[i] = r[i];
    }
    double wp[8];
    #pragma unroll
    for (int i = 0; i < 8; i++)
        wp[i] = pack2(g_Kvec[(15 - 2 * i) * 64 + n], g_Kvec[(14 - 2 * i) * 64 + n]);

    float cmy = 0.0f;
    c_sm[0][n] = 0.0f;

    for (int k = 0; k < NCHUNK; k++) {
        const int buf = k & 1;
        const size_t col = (size_t)k * NSEQ + seq;
        {
            const __half h = __float2half(cmy);
            g_Xhi[col * KREAL + n] = h;
            g_Xlo[col * KREAL + n] = __float2half(cmy - __half2float(h));
        }
        if (n < 16) {
            const float f = xin[(size_t)seq * SEQLEN + k * TCH + n];
            f_sm[buf][n] = f;
            const __half h = __float2half(f);
            g_Xhi[col * KREAL + 64 + n] = h;
            g_Xlo[col * KREAL + 64 + n] = __float2half(f - __half2float(h));
        }
        __syncthreads();

        const double2* cp = reinterpret_cast<const double2*>(c_sm[buf]);
        double acc0 = 0.0, acc1 = 0.0, acc2 = 0.0, acc3 = 0.0;
        #pragma unroll
        for (int i = 0; i < 8; i++) {
            const double2 ca = cp[2 * i], cb = cp[2 * i + 1];
            acc0 = fma2(a16[4 * i],     ca.x, acc0);
            acc1 = fma2(a16[4 * i + 1], ca.y, acc1);
            acc2 = fma2(a16[4 * i + 2], cb.x, acc2);
            acc3 = fma2(a16[4 * i + 3], cb.y, acc3);
        }
        const double* fp = reinterpret_cast<const double*>(f_sm[buf]);
        acc0 = fma2(wp[0], fp[0], acc0); acc1 = fma2(wp[1], fp[1], acc1);
        acc2 = fma2(wp[2], fp[2], acc2); acc3 = fma2(wp[3], fp[3], acc3);
        acc0 = fma2(wp[4], fp[4], acc0); acc1 = fma2(wp[5], fp[5], acc1);
        acc2 = fma2(wp[6], fp[6], acc2); acc3 = fma2(wp[7], fp[7], acc3);

        const double s = add2(add2(acc0, acc1), add2(acc2, acc3));
        float x, y;
        unpack2(s, x, y);
        cmy = x + y;
        c_sm[buf ^ 1][n] = cmy;
    }
}

// ============================================================================
// GEMM: grid (1024, 2) x 128 thr.  CTA: 64 X-cols, 8 jt values.
// Arena 45056 B: [Xhi 11264 | Xlo 11264 | Gbuf0 11264 | Gbuf1 11264].
// A-fragments re-ldsm'd per jt from resident X (low regs -> 5 CTAs/SM).
// ============================================================================
__global__ __launch_bounds__(128) void gemm_kernel(float* __restrict__ out) {
    __shared__ __align__(16) char arena[45056];

    const int tid = threadIdx.x;
    const int w = tid >> 5, l = tid & 31;
    const int mbase = blockIdx.x * 64;
    const int j0    = blockIdx.y * 8;
    const uint32_t base = smem_u32(arena);

    const int hf  = tid >> 6;
    const int row = tid & 63;

    // ---- prologue: X (hi+lo) and G(j0) -> buf0 ----
    {
        const __half* xs = (hf ? g_Xlo : g_Xhi) + (size_t)(mbase + row) * KREAL;
        const uint32_t xd = base + hf * 11264 + row * KPADB;
        #pragma unroll
        for (int v = 0; v < 10; v++) cp_async16(xd + v * 16, (const char*)xs + v * 16);

        const __half* gs = g_Gh + (size_t)(j0 * 64 + row) * KREAL;
        const uint32_t gd = base + 22528 + row * KPADB;
        #pragma unroll
        for (int v = 0; v < 5; v++) {
            const int vv = hf * 5 + v;
            cp_async16(gd + vv * 16, (const char*)gs + vv * 16);
        }
        cp_commit(); cp_wait0();
    }
    __syncthreads();

    const int m0w = (w & 1) * 32;
    const int n0w = (w >> 1) * 32;
    const uint32_t aoff = base + (uint32_t)(m0w + (l & 15)) * KPADB + ((l >> 4) * 16);
    const uint32_t boff = (uint32_t)(n0w + (l & 7) + ((l & 16) >> 1)) * KPADB + ((l & 8) << 1);

    const int chunk = mbase >> 11;
    const int seqb  = mbase & 2047;

    for (int ii = 0; ii < 8; ii++) {
        const int i   = j0 + ii;
        const int cur = ii & 1;

        if (ii < 7) {   // prefetch G(i+1) into the other buffer
            const __half* gs = g_Gh + (size_t)((i + 1) * 64 + row) * KREAL;
            const uint32_t gd = base + 22528 + (cur ^ 1) * 11264 + row * KPADB;
            #pragma unroll
            for (int v = 0; v < 5; v++) {
                const int vv = hf * 5 + v;
                cp_async16(gd + vv * 16, (const char*)gs + vv * 16);
            }
            cp_commit();
        }

        float acc[2][4][4];
        #pragma unroll
        for (int mt = 0; mt < 2; mt++)
            #pragma unroll
            for (int nt = 0; nt < 4; nt++)
                #pragma unroll
                for (int q = 0; q < 4; q++) acc[mt][nt][q] = 0.0f;

        const uint32_t gb = base + 22528 + cur * 11264 + boff;
        #pragma unroll
        for (int ks = 0; ks < 5; ks++) {
            uint32_t bh[2][4];
            #pragma unroll
            for (int p = 0; p < 2; p++)
                ldsm_x4(bh[p], gb + p * (16 * KPADB) + ks * 32);
            #pragma unroll
            for (int mt = 0; mt < 2; mt++) {
                const uint32_t ad = aoff + mt * (16 * KPADB) + ks * 32;
                uint32_t ah4[4], al4[4];
                ldsm_x4(ah4, ad);
                ldsm_x4(al4, ad + 11264);
                #pragma unroll
                for (int p = 0; p < 2; p++)
                    #pragma unroll
                    for (int hh = 0; hh < 2; hh++) {
                        const int nt = p * 2 + hh;
                        mma16816(acc[mt][nt], ah4, bh[p][2 * hh], bh[p][2 * hh + 1]);
                        mma16816(acc[mt][nt], al4, bh[p][2 * hh], bh[p][2 * hh + 1]);
                    }
            }
        }

        // ---- epilogue for jt = i ----
        {
            float* obase = out + (size_t)(chunk * TCH + i) * NSEQ * 64 + n0w + (l & 3) * 2;
            #pragma unroll
            for (int mt = 0; mt < 2; mt++)
                #pragma unroll
                for (int s = 0; s < 2; s++) {
                    const int m = m0w + mt * 16 + (l >> 2) + s * 8;
                    float* ob = obase + (size_t)(seqb + m) * 64;
                    #pragma unroll
                    for (int nt = 0; nt < 4; nt++) {
                        float2 v = make_float2(acc[mt][nt][2 * s], acc[mt][nt][2 * s + 1]);
                        *reinterpret_cast<float2*>(ob + nt * 8) = v;
                    }
                }
        }

        if (ii < 7) cp_wait0();
        __syncthreads();
    }
}

// ============================================================================
extern "C" void kernel_launch(void* const* d_in, const int* in_sizes, int n_in,
                              void* d_out, int out_size) {
    const float* xin  = (const float*)d_in[0];  // (16,128,512)
    const float* Amat = (const float*)d_in[1];  // (64,64)
    const float* Bvec = (const float*)d_in[2];  // (64,)
    float* out = (float*)d_out;                 // (512,16,128,64)

    prep_kernel<<<16, 1024>>>(Amat, Bvec);
    phase1_kernel<<<NSEQ, 64>>>(xin);
    dim3 ggrid(NCOLS / 64, 2);
    gemm_kernel<<<ggrid, 128>>>(out);
}

// round 9
// speedup vs baseline: 1.0583x; 1.0583x over previous
#include <cuda_runtime.h>
#include <cuda_fp16.h>
#include <cstdint>

// ============================================================================
// HiPPO-LegT scan via chunked GEMM on mma.sync (HMMA fp16, base sm_103).
//   c_t = A c_{t-1} + f_t B ;  out (512, 2048, 64)
// Chunk T=16:  OUT[c][(j,n)] = sum_k X[c][k] * G[(j,n)][k],  K = 80.
// R9: SINGLE fp16 pass (X fp16, G fp16) -> predicted rel_err ~5e-4.
// Prep: 2 launches, register-blocked 64^3 matmuls (~2us each):
//   prep_a (1 CTA): A^2,A^4,A^8,A^16 chain + K-vec doubling
//   prep_b (16 CTAs): A^(j+1) = product of stored squares, G build
// ============================================================================

static constexpr int TCH    = 16;
static constexpr int NCHUNK = 32;
static constexpr int NSEQ   = 2048;
static constexpr int NCOLS  = NSEQ * NCHUNK;   // 65536
static constexpr int KREAL  = 80;
static constexpr int SEQLEN = 512;
static constexpr int KPADB  = 176;             // smem row pitch bytes (88 halves)

// ---- device scratch (static; no cudaMalloc) ----
__device__ __align__(16) float   g_sq[3][4096];     // A^2, A^4, A^8
__device__ __align__(16) float   g_Apow16[4096];
__device__ __align__(16) float   g_Kvec[16 * 64];
__device__ __align__(16) __half  g_Gh[1024 * KREAL];
__device__ __align__(16) __half  g_Xh[(size_t)NCOLS * KREAL];

// ---- packed f32x2 helpers ----
__device__ __forceinline__ double fma2(double a, double b, double c) {
    double d; asm("fma.rn.f32x2 %0, %1, %2, %3;" : "=d"(d) : "d"(a), "d"(b), "d"(c)); return d;
}
__device__ __forceinline__ double add2(double a, double b) {
    double d; asm("add.rn.f32x2 %0, %1, %2;" : "=d"(d) : "d"(a), "d"(b)); return d;
}
__device__ __forceinline__ double pack2(float lo, float hi) {
    double d; asm("mov.b64 %0, {%1, %2};" : "=d"(d) : "f"(lo), "f"(hi)); return d;
}
__device__ __forceinline__ void unpack2(double d, float& lo, float& hi) {
    asm("mov.b64 {%0, %1}, %2;" : "=f"(lo), "=f"(hi) : "d"(d));
}

// ---- mma / ldmatrix / cp.async ----
__device__ __forceinline__ uint32_t smem_u32(const void* p) {
    uint32_t a;
    asm("{ .reg .u64 t; cvta.to.shared.u64 t, %1; cvt.u32.u64 %0, t; }" : "=r"(a) : "l"(p));
    return a;
}
__device__ __forceinline__ void mma16816(float* d, const uint32_t* a, uint32_t b0, uint32_t b1) {
    asm volatile(
        "mma.sync.aligned.m16n8k16.row.col.f32.f16.f16.f32 "
        "{%0,%1,%2,%3}, {%4,%5,%6,%7}, {%8,%9}, {%0,%1,%2,%3};\n"
        : "+f"(d[0]), "+f"(d[1]), "+f"(d[2]), "+f"(d[3])
        : "r"(a[0]), "r"(a[1]), "r"(a[2]), "r"(a[3]), "r"(b0), "r"(b1));
}
__device__ __forceinline__ void ldsm_x4(uint32_t* r, uint32_t addr) {
    asm volatile("ldmatrix.sync.aligned.m8n8.x4.shared.b16 {%0,%1,%2,%3}, [%4];"
                 : "=r"(r[0]), "=r"(r[1]), "=r"(r[2]), "=r"(r[3]) : "r"(addr));
}
__device__ __forceinline__ void cp_async16(uint32_t smem, const void* g) {
    asm volatile("cp.async.cg.shared.global [%0], [%1], 16;" :: "r"(smem), "l"(g));
}
__device__ __forceinline__ void cp_commit() { asm volatile("cp.async.commit_group;" ::: "memory"); }
__device__ __forceinline__ void cp_wait0()  { asm volatile("cp.async.wait_group 0;"  ::: "memory"); }

// ---- register-blocked 64x64x64 matmul: D = L @ R, 256 active threads ----
// Thread (t<256): rows r0=(t>>4)*4 .. +3, cols c0=(t&15)*4 .. +3.
// R loads broadcast-dedup across half-warps; ~2us on one SM.
__device__ __forceinline__ void mm64(const float* __restrict__ L,
                                     const float* __restrict__ R,
                                     float* __restrict__ D, int t) {
    if (t < 256) {
        const int r0 = (t >> 4) * 4;
        const int c4 = (t & 15);
        const float4* L4 = reinterpret_cast<const float4*>(L);
        const float4* R4 = reinterpret_cast<const float4*>(R);
        float4 acc0 = make_float4(0.f, 0.f, 0.f, 0.f);
        float4 acc1 = acc0, acc2 = acc0, acc3 = acc0;
        #pragma unroll
        for (int v = 0; v < 16; v++) {
            const float4 a0 = L4[(r0 + 0) * 16 + v];
            const float4 a1 = L4[(r0 + 1) * 16 + v];
            const float4 a2 = L4[(r0 + 2) * 16 + v];
            const float4 a3 = L4[(r0 + 3) * 16 + v];
            const float4 b0 = R4[(4 * v + 0) * 16 + c4];
            const float4 b1 = R4[(4 * v + 1) * 16 + c4];
            const float4 b2 = R4[(4 * v + 2) * 16 + c4];
            const float4 b3 = R4[(4 * v + 3) * 16 + c4];
            acc0.x = fmaf(a0.x, b0.x, acc0.x); acc0.y = fmaf(a0.x, b0.y, acc0.y);
            acc0.z = fmaf(a0.x, b0.z, acc0.z); acc0.w = fmaf(a0.x, b0.w, acc0.w);
            acc0.x = fmaf(a0.y, b1.x, acc0.x); acc0.y = fmaf(a0.y, b1.y, acc0.y);
            acc0.z = fmaf(a0.y, b1.z, acc0.z); acc0.w = fmaf(a0.y, b1.w, acc0.w);
            acc0.x = fmaf(a0.z, b2.x, acc0.x); acc0.y = fmaf(a0.z, b2.y, acc0.y);
            acc0.z = fmaf(a0.z, b2.z, acc0.z); acc0.w = fmaf(a0.z, b2.w, acc0.w);
            acc0.x = fmaf(a0.w, b3.x, acc0.x); acc0.y = fmaf(a0.w, b3.y, acc0.y);
            acc0.z = fmaf(a0.w, b3.z, acc0.z); acc0.w = fmaf(a0.w, b3.w, acc0.w);

            acc1.x = fmaf(a1.x, b0.x, acc1.x); acc1.y = fmaf(a1.x, b0.y, acc1.y);
            acc1.z = fmaf(a1.x, b0.z, acc1.z); acc1.w = fmaf(a1.x, b0.w, acc1.w);
            acc1.x = fmaf(a1.y, b1.x, acc1.x); acc1.y = fmaf(a1.y, b1.y, acc1.y);
            acc1.z = fmaf(a1.y, b1.z, acc1.z); acc1.w = fmaf(a1.y, b1.w, acc1.w);
            acc1.x = fmaf(a1.z, b2.x, acc1.x); acc1.y = fmaf(a1.z, b2.y, acc1.y);
            acc1.z = fmaf(a1.z, b2.z, acc1.z); acc1.w = fmaf(a1.z, b2.w, acc1.w);
            acc1.x = fmaf(a1.w, b3.x, acc1.x); acc1.y = fmaf(a1.w, b3.y, acc1.y);
            acc1.z = fmaf(a1.w, b3.z, acc1.z); acc1.w = fmaf(a1.w, b3.w, acc1.w);

            acc2.x = fmaf(a2.x, b0.x, acc2.x); acc2.y = fmaf(a2.x, b0.y, acc2.y);
            acc2.z = fmaf(a2.x, b0.z, acc2.z); acc2.w = fmaf(a2.x, b0.w, acc2.w);
            acc2.x = fmaf(a2.y, b1.x, acc2.x); acc2.y = fmaf(a2.y, b1.y, acc2.y);
            acc2.z = fmaf(a2.y, b1.z, acc2.z); acc2.w = fmaf(a2.y, b1.w, acc2.w);
            acc2.x = fmaf(a2.z, b2.x, acc2.x); acc2.y = fmaf(a2.z, b2.y, acc2.y);
            acc2.z = fmaf(a2.z, b2.z, acc2.z); acc2.w = fmaf(a2.z, b2.w, acc2.w);
            acc2.x = fmaf(a2.w, b3.x, acc2.x); acc2.y = fmaf(a2.w, b3.y, acc2.y);
            acc2.z = fmaf(a2.w, b3.z, acc2.z); acc2.w = fmaf(a2.w, b3.w, acc2.w);

            acc3.x = fmaf(a3.x, b0.x, acc3.x); acc3.y = fmaf(a3.x, b0.y, acc3.y);
            acc3.z = fmaf(a3.x, b0.z, acc3.z); acc3.w = fmaf(a3.x, b0.w, acc3.w);
            acc3.x = fmaf(a3.y, b1.x, acc3.x); acc3.y = fmaf(a3.y, b1.y, acc3.y);
            acc3.z = fmaf(a3.y, b1.z, acc3.z); acc3.w = fmaf(a3.y, b1.w, acc3.w);
            acc3.x = fmaf(a3.z, b2.x, acc3.x); acc3.y = fmaf(a3.z, b2.y, acc3.y);
            acc3.z = fmaf(a3.z, b2.z, acc3.z); acc3.w = fmaf(a3.z, b2.w, acc3.w);
            acc3.x = fmaf(a3.w, b3.x, acc3.x); acc3.y = fmaf(a3.w, b3.y, acc3.y);
            acc3.z = fmaf(a3.w, b3.z, acc3.z); acc3.w = fmaf(a3.w, b3.w, acc3.w);
        }
        float4* D4 = reinterpret_cast<float4*>(D);
        D4[(r0 + 0) * 16 + c4] = acc0;
        D4[(r0 + 1) * 16 + c4] = acc1;
        D4[(r0 + 2) * 16 + c4] = acc2;
        D4[(r0 + 3) * 16 + c4] = acc3;
    }
    __syncthreads();
}

// ============================================================================
// prep_a: 1 CTA x 1024 threads.  Squares chain + K-vector doubling.
// ============================================================================
__global__ __launch_bounds__(1024) void prep_a_kernel(const float* __restrict__ A,
                                                      const float* __restrict__ Bvec) {
    __shared__ __align__(16) float sX[4096];
    __shared__ __align__(16) float sY[4096];
    __shared__ __align__(16) float sK[16 * 64];
    const int t = threadIdx.x;

    for (int i = t; i < 4096; i += 1024) sX[i] = A[i];
    if (t < 64) sK[t] = Bvec[t];
    __syncthreads();

    // K1 = A @ K0
    if (t < 64) {
        float s = 0.f;
        #pragma unroll
        for (int m = 0; m < 64; m++) s = fmaf(sX[t * 64 + m], sK[m], s);
        sK[64 + t] = s;
    }
    __syncthreads();

    mm64(sX, sX, sY, t);                         // S2 -> sY
    for (int i = t; i < 4096; i += 1024) g_sq[0][i] = sY[i];

    // K2,K3 = S2 @ {K0,K1}
    if (t < 128) {
        const int v = t >> 6, n = t & 63;
        float s = 0.f;
        #pragma unroll
        for (int m = 0; m < 64; m++) s = fmaf(sY[n * 64 + m], sK[v * 64 + m], s);
        sK[(2 + v) * 64 + n] = s;
    }
    __syncthreads();

    mm64(sY, sY, sX, t);                         // S4 -> sX (A dead)
    for (int i = t; i < 4096; i += 1024) g_sq[1][i] = sX[i];

    // K4..7 = S4 @ K0..3
    if (t < 256) {
        const int v = t >> 6, n = t & 63;
        float s = 0.f;
        #pragma unroll
        for (int m = 0; m < 64; m++) s = fmaf(sX[n * 64 + m], sK[v * 64 + m], s);
        sK[(4 + v) * 64 + n] = s;
    }
    __syncthreads();

    mm64(sX, sX, sY, t);                         // S8 -> sY
    for (int i = t; i < 4096; i += 1024) g_sq[2][i] = sY[i];

    // K8..15 = S8 @ K0..7
    if (t < 512) {
        const int v = t >> 6, n = t & 63;
        float s = 0.f;
        #pragma unroll
        for (int m = 0; m < 64; m++) s = fmaf(sY[n * 64 + m], sK[v * 64 + m], s);
        sK[(8 + v) * 64 + n] = s;
    }
    __syncthreads();

    mm64(sY, sY, sX, t);                         // S16 -> sX
    for (int i = t; i < 4096; i += 1024) g_Apow16[i] = sX[i];
    g_Kvec[t & 1023] = sK[t & 1023];
}

// ============================================================================
// prep_b: 16 CTAs x 1024 threads.  CTA j: A^(j+1) from {A,S2,S4,S8}, G build.
// ============================================================================
__global__ __launch_bounds__(1024) void prep_b_kernel(const float* __restrict__ A) {
    __shared__ __align__(16) float sBuf[3][4096];   // 48KB exactly
    const int t = threadIdx.x;
    const int j = blockIdx.x;
    const int p = j + 1;

    // factor list (global pointers)
    const float* fsrc[4];
    int nf = 0;
    if (p == 16) { fsrc[0] = g_sq[2]; fsrc[1] = g_sq[2]; nf = 2; }
    else {
        if (p & 1) fsrc[nf++] = A;
        if (p & 2) fsrc[nf++] = g_sq[0];
        if (p & 4) fsrc[nf++] = g_sq[1];
        if (p & 8) fsrc[nf++] = g_sq[2];
    }

    for (int i = t; i < 4096; i += 1024) sBuf[0][i] = fsrc[0][i];
    __syncthreads();

    int cur = 0;
    for (int f = 1; f < nf; f++) {
        for (int i = t; i < 4096; i += 1024) sBuf[2][i] = fsrc[f][i];
        __syncthreads();
        mm64(sBuf[cur], sBuf[2], sBuf[cur ^ 1], t);
        cur ^= 1;
    }
    const float* P = sBuf[cur];

    // G rows: r = j*64 + n
    for (int idx = t; idx < 64 * KREAL; idx += 1024) {
        const int n = idx / KREAL, k = idx % KREAL;
        float v;
        if (k < 64) v = P[n * 64 + k];
        else {
            const int d = j - (k - 64);
            v = (d < 0) ? 0.0f : g_Kvec[d * 64 + n];
        }
        g_Gh[(size_t)(j * 64 + n) * KREAL + k] = __float2half(v);
    }
}

// ============================================================================
// Phase 1: boundary scan (fp32, f32x2) + X build (fp16). 2048 x 64.
// ============================================================================
__global__ __launch_bounds__(64) void phase1_kernel(const float* __restrict__ xin) {
    const int seq = blockIdx.x, n = threadIdx.x;
    __shared__ __align__(16) float c_sm[2][64];
    __shared__ __align__(16) float f_sm[2][16];

    double a16[32];
    {
        const double* r = reinterpret_cast<const double*>(&g_Apow16[n * 64]);
        #pragma unroll
        for (int i = 0; i < 32; i++) a16[i] = r[i];
    }
    double wp[8];
    #pragma unroll
    for (int i = 0; i < 8; i++)
        wp[i] = pack2(g_Kvec[(15 - 2 * i) * 64 + n], g_Kvec[(14 - 2 * i) * 64 + n]);

    float cmy = 0.0f;
    c_sm[0][n] = 0.0f;

    for (int k = 0; k < NCHUNK; k++) {
        const int buf = k & 1;
        const size_t col = (size_t)k * NSEQ + seq;
        g_Xh[col * KREAL + n] = __float2half(cmy);
        if (n < 16) {
            const float f = xin[(size_t)seq * SEQLEN + k * TCH + n];
            f_sm[buf][n] = f;
            g_Xh[col * KREAL + 64 + n] = __float2half(f);
        }
        __syncthreads();

        const double2* cp = reinterpret_cast<const double2*>(c_sm[buf]);
        double acc0 = 0.0, acc1 = 0.0, acc2 = 0.0, acc3 = 0.0;
        #pragma unroll
        for (int i = 0; i < 8; i++) {
            const double2 ca = cp[2 * i], cb = cp[2 * i + 1];
            acc0 = fma2(a16[4 * i],     ca.x, acc0);
            acc1 = fma2(a16[4 * i + 1], ca.y, acc1);
            acc2 = fma2(a16[4 * i + 2], cb.x, acc2);
            acc3 = fma2(a16[4 * i + 3], cb.y, acc3);
        }
        const double* fp = reinterpret_cast<const double*>(f_sm[buf]);
        acc0 = fma2(wp[0], fp[0], acc0); acc1 = fma2(wp[1], fp[1], acc1);
        acc2 = fma2(wp[2], fp[2], acc2); acc3 = fma2(wp[3], fp[3], acc3);
        acc0 = fma2(wp[4], fp[4], acc0); acc1 = fma2(wp[5], fp[5], acc1);
        acc2 = fma2(wp[6], fp[6], acc2); acc3 = fma2(wp[7], fp[7], acc3);

        const double s = add2(add2(acc0, acc1), add2(acc2, acc3));
        float x, y;
        unpack2(s, x, y);
        cmy = x + y;
        c_sm[buf ^ 1][n] = cmy;
    }
}

// ============================================================================
// GEMM: grid (1024, 2) x 128 thr.  CTA: 64 X-cols, 8 jt values, single pass.
// Arena 33792 B: [Xh 11264 | Gbuf0 11264 | Gbuf1 11264].
// ============================================================================
__global__ __launch_bounds__(128) void gemm_kernel(float* __restrict__ out) {
    __shared__ __align__(16) char arena[33792];

    const int tid = threadIdx.x;
    const int w = tid >> 5, l = tid & 31;
    const int mbase = blockIdx.x * 64;
    const int j0    = blockIdx.y * 8;
    const uint32_t base = smem_u32(arena);

    const int row = tid >> 1;            // 0..63
    const int prt = tid & 1;             // half of the 160B row

    // ---- prologue: Xh tile + G(j0) -> buf0 ----
    {
        const __half* xs = g_Xh + (size_t)(mbase + row) * KREAL;
        const uint32_t xd = base + row * KPADB;
        #pragma unroll
        for (int v = 0; v < 5; v++) {
            const int vv = prt * 5 + v;
            cp_async16(xd + vv * 16, (const char*)xs + vv * 16);
        }
        const __half* gs = g_Gh + (size_t)(j0 * 64 + row) * KREAL;
        const uint32_t gd = base + 11264 + row * KPADB;
        #pragma unroll
        for (int v = 0; v < 5; v++) {
            const int vv = prt * 5 + v;
            cp_async16(gd + vv * 16, (const char*)gs + vv * 16);
        }
        cp_commit(); cp_wait0();
    }
    __syncthreads();

    const int m0w = (w & 1) * 32;
    const int n0w = (w >> 1) * 32;
    const uint32_t aoff = base + (uint32_t)(m0w + (l & 15)) * KPADB + ((l >> 4) * 16);
    const uint32_t boff = (uint32_t)(n0w + (l & 7) + ((l & 16) >> 1)) * KPADB + ((l & 8) << 1);

    const int chunk = mbase >> 11;
    const int seqb  = mbase & 2047;

    for (int ii = 0; ii < 8; ii++) {
        const int i   = j0 + ii;
        const int cur = ii & 1;

        if (ii < 7) {   // prefetch G(i+1) into the other buffer
            const __half* gs = g_Gh + (size_t)((i + 1) * 64 + row) * KREAL;
            const uint32_t gd = base + 11264 + (cur ^ 1) * 11264 + row * KPADB;
            #pragma unroll
            for (int v = 0; v < 5; v++) {
                const int vv = prt * 5 + v;
                cp_async16(gd + vv * 16, (const char*)gs + vv * 16);
            }
            cp_commit();
        }

        float acc[2][4][4];
        #pragma unroll
        for (int mt = 0; mt < 2; mt++)
            #pragma unroll
            for (int nt = 0; nt < 4; nt++)
                #pragma unroll
                for (int q = 0; q < 4; q++) acc[mt][nt][q] = 0.0f;

        const uint32_t gb = base + 11264 + cur * 11264 + boff;
        #pragma unroll
        for (int ks = 0; ks < 5; ks++) {
            uint32_t bh[2][4];
            #pragma unroll
            for (int p = 0; p < 2; p++)
                ldsm_x4(bh[p], gb + p * (16 * KPADB) + ks * 32);
            #pragma unroll
            for (int mt = 0; mt < 2; mt++) {
                uint32_t ah4[4];
                ldsm_x4(ah4, aoff + mt * (16 * KPADB) + ks * 32);
                #pragma unroll
                for (int p = 0; p < 2; p++)
                    #pragma unroll
                    for (int hh = 0; hh < 2; hh++)
                        mma16816(acc[mt][p * 2 + hh], ah4, bh[p][2 * hh], bh[p][2 * hh + 1]);
            }
        }

        // ---- epilogue for jt = i ----
        {
            float* obase = out + (size_t)(chunk * TCH + i) * NSEQ * 64 + n0w + (l & 3) * 2;
            #pragma unroll
            for (int mt = 0; mt < 2; mt++)
                #pragma unroll
                for (int s = 0; s < 2; s++) {
                    const int m = m0w + mt * 16 + (l >> 2) + s * 8;
                    float* ob = obase + (size_t)(seqb + m) * 64;
                    #pragma unroll
                    for (int nt = 0; nt < 4; nt++) {
                        float2 v = make_float2(acc[mt][nt][2 * s], acc[mt][nt][2 * s + 1]);
                        *reinterpret_cast<float2*>(ob + nt * 8) = v;
                    }
                }
        }

        if (ii < 7) cp_wait0();
        __syncthreads();
    }
}

// ============================================================================
extern "C" void kernel_launch(void* const* d_in, const int* in_sizes, int n_in,
                              void* d_out, int out_size) {
    const float* xin  = (const float*)d_in[0];  // (16,128,512)
    const float* Amat = (const float*)d_in[1];  // (64,64)
    const float* Bvec = (const float*)d_in[2];  // (64,)
    float* out = (float*)d_out;                 // (512,16,128,64)

    prep_a_kernel<<<1, 1024>>>(Amat, Bvec);
    prep_b_kernel<<<16, 1024>>>(Amat);
    phase1_kernel<<<NSEQ, 64>>>(xin);
    dim3 ggrid(NCOLS / 64, 2);
    gemm_kernel<<<ggrid, 128>>>(out);
}

// round 10
// speedup vs baseline: 1.5134x; 1.4300x over previous
#include <cuda_runtime.h>
#include <cuda_fp16.h>
#include <cstdint>

// ============================================================================
// HiPPO-LegT scan via chunked GEMM on mma.sync (HMMA fp16, base sm_103).
//   c_t = A c_{t-1} + f_t B ;  out (512, 2048, 64)
// Chunk T=16:  OUT[c][(j,n)] = sum_k X[c][k] * G[(j,n)][k],  K = 80.
// Single fp16 pass (validated R9: rel_err 2.9e-4).
// R10: barrier-free GEMM — one-shot tiles (X 128 cols + 2 jt G), one barrier,
// then 8 fully independent warps (32Mx64Nx80K each), streaming stores.
// ============================================================================

static constexpr int TCH    = 16;
static constexpr int NCHUNK = 32;
static constexpr int NSEQ   = 2048;
static constexpr int NCOLS  = NSEQ * NCHUNK;   // 65536
static constexpr int KREAL  = 80;
static constexpr int SEQLEN = 512;
static constexpr int KPADB  = 176;             // smem row pitch bytes (88 halves)
static constexpr int MT     = 128;             // X columns per CTA

// ---- device scratch (static; no cudaMalloc) ----
__device__ __align__(16) float   g_sq[3][4096];     // A^2, A^4, A^8
__device__ __align__(16) float   g_Apow16[4096];
__device__ __align__(16) float   g_Kvec[16 * 64];
__device__ __align__(16) __half  g_Gh[1024 * KREAL];
__device__ __align__(16) __half  g_Xh[(size_t)NCOLS * KREAL];

// ---- packed f32x2 helpers ----
__device__ __forceinline__ double fma2(double a, double b, double c) {
    double d; asm("fma.rn.f32x2 %0, %1, %2, %3;" : "=d"(d) : "d"(a), "d"(b), "d"(c)); return d;
}
__device__ __forceinline__ double add2(double a, double b) {
    double d; asm("add.rn.f32x2 %0, %1, %2;" : "=d"(d) : "d"(a), "d"(b)); return d;
}
__device__ __forceinline__ double pack2(float lo, float hi) {
    double d; asm("mov.b64 %0, {%1, %2};" : "=d"(d) : "f"(lo), "f"(hi)); return d;
}
__device__ __forceinline__ void unpack2(double d, float& lo, float& hi) {
    asm("mov.b64 {%0, %1}, %2;" : "=f"(lo), "=f"(hi) : "d"(d));
}

// ---- mma / ldmatrix / cp.async ----
__device__ __forceinline__ uint32_t smem_u32(const void* p) {
    uint32_t a;
    asm("{ .reg .u64 t; cvta.to.shared.u64 t, %1; cvt.u32.u64 %0, t; }" : "=r"(a) : "l"(p));
    return a;
}
__device__ __forceinline__ void mma16816(float* d, const uint32_t* a, uint32_t b0, uint32_t b1) {
    asm volatile(
        "mma.sync.aligned.m16n8k16.row.col.f32.f16.f16.f32 "
        "{%0,%1,%2,%3}, {%4,%5,%6,%7}, {%8,%9}, {%0,%1,%2,%3};\n"
        : "+f"(d[0]), "+f"(d[1]), "+f"(d[2]), "+f"(d[3])
        : "r"(a[0]), "r"(a[1]), "r"(a[2]), "r"(a[3]), "r"(b0), "r"(b1));
}
__device__ __forceinline__ void ldsm_x4(uint32_t* r, uint32_t addr) {
    asm volatile("ldmatrix.sync.aligned.m8n8.x4.shared.b16 {%0,%1,%2,%3}, [%4];"
                 : "=r"(r[0]), "=r"(r[1]), "=r"(r[2]), "=r"(r[3]) : "r"(addr));
}
__device__ __forceinline__ void cp_async16(uint32_t smem, const void* g) {
    asm volatile("cp.async.cg.shared.global [%0], [%1], 16;" :: "r"(smem), "l"(g));
}
__device__ __forceinline__ void cp_commit() { asm volatile("cp.async.commit_group;" ::: "memory"); }
__device__ __forceinline__ void cp_wait0()  { asm volatile("cp.async.wait_group 0;"  ::: "memory"); }

// ---- register-blocked 64x64x64 matmul: D = L @ R, 256 active threads ----
__device__ __forceinline__ void mm64(const float* __restrict__ L,
                                     const float* __restrict__ R,
                                     float* __restrict__ D, int t) {
    if (t < 256) {
        const int r0 = (t >> 4) * 4;
        const int c4 = (t & 15);
        const float4* L4 = reinterpret_cast<const float4*>(L);
        const float4* R4 = reinterpret_cast<const float4*>(R);
        float4 acc0 = make_float4(0.f, 0.f, 0.f, 0.f);
        float4 acc1 = acc0, acc2 = acc0, acc3 = acc0;
        #pragma unroll
        for (int v = 0; v < 16; v++) {
            const float4 a0 = L4[(r0 + 0) * 16 + v];
            const float4 a1 = L4[(r0 + 1) * 16 + v];
            const float4 a2 = L4[(r0 + 2) * 16 + v];
            const float4 a3 = L4[(r0 + 3) * 16 + v];
            const float4 b0 = R4[(4 * v + 0) * 16 + c4];
            const float4 b1 = R4[(4 * v + 1) * 16 + c4];
            const float4 b2 = R4[(4 * v + 2) * 16 + c4];
            const float4 b3 = R4[(4 * v + 3) * 16 + c4];
            acc0.x = fmaf(a0.x, b0.x, acc0.x); acc0.y = fmaf(a0.x, b0.y, acc0.y);
            acc0.z = fmaf(a0.x, b0.z, acc0.z); acc0.w = fmaf(a0.x, b0.w, acc0.w);
            acc0.x = fmaf(a0.y, b1.x, acc0.x); acc0.y = fmaf(a0.y, b1.y, acc0.y);
            acc0.z = fmaf(a0.y, b1.z, acc0.z); acc0.w = fmaf(a0.y, b1.w, acc0.w);
            acc0.x = fmaf(a0.z, b2.x, acc0.x); acc0.y = fmaf(a0.z, b2.y, acc0.y);
            acc0.z = fmaf(a0.z, b2.z, acc0.z); acc0.w = fmaf(a0.z, b2.w, acc0.w);
            acc0.x = fmaf(a0.w, b3.x, acc0.x); acc0.y = fmaf(a0.w, b3.y, acc0.y);
            acc0.z = fmaf(a0.w, b3.z, acc0.z); acc0.w = fmaf(a0.w, b3.w, acc0.w);

            acc1.x = fmaf(a1.x, b0.x, acc1.x); acc1.y = fmaf(a1.x, b0.y, acc1.y);
            acc1.z = fmaf(a1.x, b0.z, acc1.z); acc1.w = fmaf(a1.x, b0.w, acc1.w);
            acc1.x = fmaf(a1.y, b1.x, acc1.x); acc1.y = fmaf(a1.y, b1.y, acc1.y);
            acc1.z = fmaf(a1.y, b1.z, acc1.z); acc1.w = fmaf(a1.y, b1.w, acc1.w);
            acc1.x = fmaf(a1.z, b2.x, acc1.x); acc1.y = fmaf(a1.z, b2.y, acc1.y);
            acc1.z = fmaf(a1.z, b2.z, acc1.z); acc1.w = fmaf(a1.z, b2.w, acc1.w);
            acc1.x = fmaf(a1.w, b3.x, acc1.x); acc1.y = fmaf(a1.w, b3.y, acc1.y);
            acc1.z = fmaf(a1.w, b3.z, acc1.z); acc1.w = fmaf(a1.w, b3.w, acc1.w);

            acc2.x = fmaf(a2.x, b0.x, acc2.x); acc2.y = fmaf(a2.x, b0.y, acc2.y);
            acc2.z = fmaf(a2.x, b0.z, acc2.z); acc2.w = fmaf(a2.x, b0.w, acc2.w);
            acc2.x = fmaf(a2.y, b1.x, acc2.x); acc2.y = fmaf(a2.y, b1.y, acc2.y);
            acc2.z = fmaf(a2.y, b1.z, acc2.z); acc2.w = fmaf(a2.y, b1.w, acc2.w);
            acc2.x = fmaf(a2.z, b2.x, acc2.x); acc2.y = fmaf(a2.z, b2.y, acc2.y);
            acc2.z = fmaf(a2.z, b2.z, acc2.z); acc2.w = fmaf(a2.z, b2.w, acc2.w);
            acc2.x = fmaf(a2.w, b3.x, acc2.x); acc2.y = fmaf(a2.w, b3.y, acc2.y);
            acc2.z = fmaf(a2.w, b3.z, acc2.z); acc2.w = fmaf(a2.w, b3.w, acc2.w);

            acc3.x = fmaf(a3.x, b0.x, acc3.x); acc3.y = fmaf(a3.x, b0.y, acc3.y);
            acc3.z = fmaf(a3.x, b0.z, acc3.z); acc3.w = fmaf(a3.x, b0.w, acc3.w);
            acc3.x = fmaf(a3.y, b1.x, acc3.x); acc3.y = fmaf(a3.y, b1.y, acc3.y);
            acc3.z = fmaf(a3.y, b1.z, acc3.z); acc3.w = fmaf(a3.y, b1.w, acc3.w);
            acc3.x = fmaf(a3.z, b2.x, acc3.x); acc3.y = fmaf(a3.z, b2.y, acc3.y);
            acc3.z = fmaf(a3.z, b2.z, acc3.z); acc3.w = fmaf(a3.z, b2.w, acc3.w);
            acc3.x = fmaf(a3.w, b3.x, acc3.x); acc3.y = fmaf(a3.w, b3.y, acc3.y);
            acc3.z = fmaf(a3.w, b3.z, acc3.z); acc3.w = fmaf(a3.w, b3.w, acc3.w);
        }
        float4* D4 = reinterpret_cast<float4*>(D);
        D4[(r0 + 0) * 16 + c4] = acc0;
        D4[(r0 + 1) * 16 + c4] = acc1;
        D4[(r0 + 2) * 16 + c4] = acc2;
        D4[(r0 + 3) * 16 + c4] = acc3;
    }
    __syncthreads();
}

// ============================================================================
// prep_a: 1 CTA x 1024 threads.  Squares chain + K-vector doubling.
// ============================================================================
__global__ __launch_bounds__(1024) void prep_a_kernel(const float* __restrict__ A,
                                                      const float* __restrict__ Bvec) {
    __shared__ __align__(16) float sX[4096];
    __shared__ __align__(16) float sY[4096];
    __shared__ __align__(16) float sK[16 * 64];
    const int t = threadIdx.x;

    for (int i = t; i < 4096; i += 1024) sX[i] = A[i];
    if (t < 64) sK[t] = Bvec[t];
    __syncthreads();

    if (t < 64) {
        float s = 0.f;
        #pragma unroll
        for (int m = 0; m < 64; m++) s = fmaf(sX[t * 64 + m], sK[m], s);
        sK[64 + t] = s;
    }
    __syncthreads();

    mm64(sX, sX, sY, t);                         // S2
    for (int i = t; i < 4096; i += 1024) g_sq[0][i] = sY[i];

    if (t < 128) {
        const int v = t >> 6, n = t & 63;
        float s = 0.f;
        #pragma unroll
        for (int m = 0; m < 64; m++) s = fmaf(sY[n * 64 + m], sK[v * 64 + m], s);
        sK[(2 + v) * 64 + n] = s;
    }
    __syncthreads();

    mm64(sY, sY, sX, t);                         // S4
    for (int i = t; i < 4096; i += 1024) g_sq[1][i] = sX[i];

    if (t < 256) {
        const int v = t >> 6, n = t & 63;
        float s = 0.f;
        #pragma unroll
        for (int m = 0; m < 64; m++) s = fmaf(sX[n * 64 + m], sK[v * 64 + m], s);
        sK[(4 + v) * 64 + n] = s;
    }
    __syncthreads();

    mm64(sX, sX, sY, t);                         // S8
    for (int i = t; i < 4096; i += 1024) g_sq[2][i] = sY[i];

    if (t < 512) {
        const int v = t >> 6, n = t & 63;
        float s = 0.f;
        #pragma unroll
        for (int m = 0; m < 64; m++) s = fmaf(sY[n * 64 + m], sK[v * 64 + m], s);
        sK[(8 + v) * 64 + n] = s;
    }
    __syncthreads();

    mm64(sY, sY, sX, t);                         // S16
    for (int i = t; i < 4096; i += 1024) g_Apow16[i] = sX[i];
    g_Kvec[t & 1023] = sK[t & 1023];
}

// ============================================================================
// prep_b: 16 CTAs x 1024 threads.  CTA j: A^(j+1) from {A,S2,S4,S8}, G build.
// ============================================================================
__global__ __launch_bounds__(1024) void prep_b_kernel(const float* __restrict__ A) {
    __shared__ __align__(16) float sBuf[3][4096];
    const int t = threadIdx.x;
    const int j = blockIdx.x;
    const int p = j + 1;

    const float* fsrc[4];
    int nf = 0;
    if (p == 16) { fsrc[0] = g_sq[2]; fsrc[1] = g_sq[2]; nf = 2; }
    else {
        if (p & 1) fsrc[nf++] = A;
        if (p & 2) fsrc[nf++] = g_sq[0];
        if (p & 4) fsrc[nf++] = g_sq[1];
        if (p & 8) fsrc[nf++] = g_sq[2];
    }

    for (int i = t; i < 4096; i += 1024) sBuf[0][i] = fsrc[0][i];
    __syncthreads();

    int cur = 0;
    for (int f = 1; f < nf; f++) {
        for (int i = t; i < 4096; i += 1024) sBuf[2][i] = fsrc[f][i];
        __syncthreads();
        mm64(sBuf[cur], sBuf[2], sBuf[cur ^ 1], t);
        cur ^= 1;
    }
    const float* P = sBuf[cur];

    for (int idx = t; idx < 64 * KREAL; idx += 1024) {
        const int n = idx / KREAL, k = idx % KREAL;
        float v;
        if (k < 64) v = P[n * 64 + k];
        else {
            const int d = j - (k - 64);
            v = (d < 0) ? 0.0f : g_Kvec[d * 64 + n];
        }
        g_Gh[(size_t)(j * 64 + n) * KREAL + k] = __float2half(v);
    }
}

// ============================================================================
// Phase 1: boundary scan (fp32, f32x2) + X build (fp16). 2048 x 64.
// ============================================================================
__global__ __launch_bounds__(64) void phase1_kernel(const float* __restrict__ xin) {
    const int seq = blockIdx.x, n = threadIdx.x;
    __shared__ __align__(16) float c_sm[2][64];
    __shared__ __align__(16) float f_sm[2][16];

    double a16[32];
    {
        const double* r = reinterpret_cast<const double*>(&g_Apow16[n * 64]);
        #pragma unroll
        for (int i = 0; i < 32; i++) a16[i] = r[i];
    }
    double wp[8];
    #pragma unroll
    for (int i = 0; i < 8; i++)
        wp[i] = pack2(g_Kvec[(15 - 2 * i) * 64 + n], g_Kvec[(14 - 2 * i) * 64 + n]);

    float cmy = 0.0f;
    c_sm[0][n] = 0.0f;

    for (int k = 0; k < NCHUNK; k++) {
        const int buf = k & 1;
        const size_t col = (size_t)k * NSEQ + seq;
        g_Xh[col * KREAL + n] = __float2half(cmy);
        if (n < 16) {
            const float f = xin[(size_t)seq * SEQLEN + k * TCH + n];
            f_sm[buf][n] = f;
            g_Xh[col * KREAL + 64 + n] = __float2half(f);
        }
        __syncthreads();

        const double2* cp = reinterpret_cast<const double2*>(c_sm[buf]);
        double acc0 = 0.0, acc1 = 0.0, acc2 = 0.0, acc3 = 0.0;
        #pragma unroll
        for (int i = 0; i < 8; i++) {
            const double2 ca = cp[2 * i], cb = cp[2 * i + 1];
            acc0 = fma2(a16[4 * i],     ca.x, acc0);
            acc1 = fma2(a16[4 * i + 1], ca.y, acc1);
            acc2 = fma2(a16[4 * i + 2], cb.x, acc2);
            acc3 = fma2(a16[4 * i + 3], cb.y, acc3);
        }
        const double* fp = reinterpret_cast<const double*>(f_sm[buf]);
        acc0 = fma2(wp[0], fp[0], acc0); acc1 = fma2(wp[1], fp[1], acc1);
        acc2 = fma2(wp[2], fp[2], acc2); acc3 = fma2(wp[3], fp[3], acc3);
        acc0 = fma2(wp[4], fp[4], acc0); acc1 = fma2(wp[5], fp[5], acc1);
        acc2 = fma2(wp[6], fp[6], acc2); acc3 = fma2(wp[7], fp[7], acc3);

        const double s = add2(add2(acc0, acc1), add2(acc2, acc3));
        float x, y;
        unpack2(s, x, y);
        cmy = x + y;
        c_sm[buf ^ 1][n] = cmy;
    }
}

// ============================================================================
// GEMM: grid (512, 8) x 256 thr.  CTA: 128 X-cols x 2 jt, ONE barrier.
// Arena 45056 B: [Xh 22528 | G(j0) 11264 | G(j0+1) 11264].
// Warp w: jt = j0 + (w>>2), M-rows [(w&3)*32, +32); fully independent.
// Streaming stores (__stcs) keep L2 for tile reads.
// ============================================================================
__global__ __launch_bounds__(256) void gemm_kernel(float* __restrict__ out) {
    __shared__ __align__(16) char arena[45056];

    const int tid = threadIdx.x;
    const int w = tid >> 5, l = tid & 31;
    const int mbase = blockIdx.x * MT;        // 512 blocks
    const int j0    = blockIdx.y * 2;         // 8 blocks
    const uint32_t base = smem_u32(arena);

    // ---- prologue: X (128 rows) + G(j0), G(j0+1) ----
    for (int c = tid; c < 1280; c += 256) {
        const int row = c / 10, part = c % 10;
        cp_async16(base + row * KPADB + part * 16,
                   (const char*)(g_Xh + (size_t)(mbase + row) * KREAL) + part * 16);
    }
    for (int c = tid; c < 1280; c += 256) {
        const int g = c / 640, rem = c % 640;
        const int row = rem / 10, part = rem % 10;
        cp_async16(base + 22528 + g * 11264 + row * KPADB + part * 16,
                   (const char*)(g_Gh + (size_t)((j0 + g) * 64 + row) * KREAL) + part * 16);
    }
    cp_commit(); cp_wait0();
    __syncthreads();

    const int jl = w >> 2;                    // 0/1
    const int mq = w & 3;                     // 0..3
    const int jt = j0 + jl;

    const uint32_t aoff = base + (uint32_t)(mq * 32 + (l & 15)) * KPADB + ((l >> 4) * 16);
    const uint32_t gbuf = base + 22528 + jl * 11264;
    const uint32_t boff = gbuf + (uint32_t)((l & 7) + ((l & 16) >> 1)) * KPADB + ((l & 8) << 1);

    float acc[2][8][4];
    #pragma unroll
    for (int mt = 0; mt < 2; mt++)
        #pragma unroll
        for (int nt = 0; nt < 8; nt++)
            #pragma unroll
            for (int q = 0; q < 4; q++) acc[mt][nt][q] = 0.0f;

    #pragma unroll
    for (int ks = 0; ks < 5; ks++) {
        uint32_t bh[4][4];
        #pragma unroll
        for (int p = 0; p < 4; p++)
            ldsm_x4(bh[p], boff + p * (16 * KPADB) + ks * 32);
        #pragma unroll
        for (int mt = 0; mt < 2; mt++) {
            uint32_t a4[4];
            ldsm_x4(a4, aoff + mt * (16 * KPADB) + ks * 32);
            #pragma unroll
            for (int p = 0; p < 4; p++)
                #pragma unroll
                for (int hh = 0; hh < 2; hh++)
                    mma16816(acc[mt][p * 2 + hh], a4, bh[p][2 * hh], bh[p][2 * hh + 1]);
        }
    }

    // ---- epilogue (streaming stores) ----
    const int chunk = mbase >> 11;
    const int seqb  = mbase & 2047;
    float* obase = out + (size_t)(chunk * TCH + jt) * NSEQ * 64 + (l & 3) * 2;
    #pragma unroll
    for (int mt = 0; mt < 2; mt++)
        #pragma unroll
        for (int s = 0; s < 2; s++) {
            const int m = mq * 32 + mt * 16 + (l >> 2) + s * 8;
            float* ob = obase + (size_t)(seqb + m) * 64;
            #pragma unroll
            for (int nt = 0; nt < 8; nt++)
                __stcs(reinterpret_cast<float2*>(ob + nt * 8),
                       make_float2(acc[mt][nt][2 * s], acc[mt][nt][2 * s + 1]));
        }
}

// ============================================================================
extern "C" void kernel_launch(void* const* d_in, const int* in_sizes, int n_in,
                              void* d_out, int out_size) {
    const float* xin  = (const float*)d_in[0];  // (16,128,512)
    const float* Amat = (const float*)d_in[1];  // (64,64)
    const float* Bvec = (const float*)d_in[2];  // (64,)
    float* out = (float*)d_out;                 // (512,16,128,64)

    prep_a_kernel<<<1, 1024>>>(Amat, Bvec);
    prep_b_kernel<<<16, 1024>>>(Amat);
    phase1_kernel<<<NSEQ, 64>>>(xin);
    dim3 ggrid(NCOLS / MT, 8);                  // (512, 8)
    gemm_kernel<<<ggrid, 256>>>(out);
}